// round 8
// baseline (speedup 1.0000x reference)
#include <cuda_runtime.h>
#include <math.h>

typedef unsigned long long u64;

__device__ __forceinline__ u64 dup2(float v){
    u64 r; asm("mov.b64 %0, {%1, %1};" : "=l"(r) : "f"(v)); return r;
}
__device__ __forceinline__ u64 pk2(float lo, float hi){
    u64 r; asm("mov.b64 %0, {%1, %2};" : "=l"(r) : "f"(lo), "f"(hi)); return r;
}
__device__ __forceinline__ void upk2(u64 a, float &lo, float &hi){
    asm("mov.b64 {%0, %1}, %2;" : "=f"(lo), "=f"(hi) : "l"(a));
}
__device__ __forceinline__ u64 fma2(u64 a, u64 b, u64 c){
    u64 d; asm("fma.rn.f32x2 %0, %1, %2, %3;" : "=l"(d) : "l"(a), "l"(b), "l"(c)); return d;
}
__device__ __forceinline__ u64 add2(u64 a, u64 b){
    u64 c; asm("add.rn.f32x2 %0, %1, %2;" : "=l"(c) : "l"(a), "l"(b)); return c;
}
__device__ __forceinline__ u64 lds2(const float* p){ return *reinterpret_cast<const u64*>(p); }

union V4 { uint4 q; u64 d[2]; };

// ---------- constant memory: pre-paired u64 operands (single LDC.64 per pair) ----------
__constant__ u64 c_W2[506];   // W1..W7; u64 offsets 0,2,10,26,58,122,250
__constant__ u64 c_B2[44];    // b1..b7; u64 offsets 0,2,4,8,12,20,28

// ---------- device globals ----------
__device__ float g_adj[576];
__device__ float g_wc[1586];    // Wc padded: node stride 66, bc at [1584..1585]

// ---------- merged prologue: adjacency + folded FC head ----------
__global__ void prologue_kernel(const int* __restrict__ ei_raw,
                                const float* __restrict__ fcw1, const float* __restrict__ fcb1,
                                const float* __restrict__ fcw2, const float* __restrict__ fcb2){
    __shared__ float sdeg[24], sdinv[24], sAl[576];
    __shared__ float sw2[256];
    __shared__ int ssrc[96], sdst[96];
    __shared__ int is64;
    int t = threadIdx.x;      // 768 threads

    if (t == 0){
        int z = 1;
        #pragma unroll 1
        for (int i = 1; i < 192; i += 2) if (ei_raw[i] != 0){ z = 0; break; }
        is64 = z;
    }
    if (t < 24) sdeg[t] = 1.0f;
    if (t < 576) sAl[t] = 0.0f;
    if (t >= 576 && t < 768) sw2[(t - 576)] = fcw2[t - 576];
    if (t < 64) sw2[192 + t] = fcw2[192 + t];
    __syncthreads();
    if (t < 96){
        int s, d;
        if (is64){
            const long long* e = reinterpret_cast<const long long*>(ei_raw);
            s = (int)e[t]; d = (int)e[96 + t];
        } else { s = ei_raw[t]; d = ei_raw[96 + t]; }
        s = min(max(s,0),23); d = min(max(d,0),23);
        ssrc[t] = s; sdst[t] = d;
        atomicAdd(&sdeg[d], 1.0f);
    }
    __syncthreads();
    if (t < 24) sdinv[t] = 1.0f / sqrtf(sdeg[t]);
    __syncthreads();
    if (t < 96) atomicAdd(&sAl[sdst[t]*24 + ssrc[t]], sdinv[ssrc[t]]*sdinv[sdst[t]]);
    if (t < 24) atomicAdd(&sAl[t*24 + t], sdinv[t]*sdinv[t]);
    __syncthreads();
    if (t < 576) g_adj[t] = sAl[t];

    // ---- Wc = fcw1 @ fcw2 (padded), bc = fcb1 @ fcw2 + fcb2 ----
    {
        float a0 = 0.f, a1 = 0.f;
        const float* row = fcw1 + t * 128;
        #pragma unroll 8
        for (int k = 0; k < 128; k++){
            float w = row[k];
            a0 += w * sw2[2*k];
            a1 += w * sw2[2*k + 1];
        }
        int node = t >> 5, fi = t & 31;
        g_wc[node*66 + 2*fi]     = a0;
        g_wc[node*66 + 2*fi + 1] = a1;
        if (t < 2){
            float b = fcb2[t];
            #pragma unroll 8
            for (int k = 0; k < 128; k++) b += fcb1[k] * sw2[2*k + t];
            g_wc[1584 + t] = b;
        }
    }
}

// ---------- fused GCN kernel ----------
#define NT 384
#define TB 16
#define RS2 20                    // ping-pong row stride
#define BST2 (24*RS2)             // 480 floats per batch

constexpr int SM_BA  = 0;         // bufA: 7680 floats
constexpr int SM_BB  = 7680;      // bufB: 7680
constexpr int SM_WC  = 15360;     // 1586
constexpr int SM_A2  = 16948;     // A pre-dup'd u64: 24*25*2 = 1200 floats (16B aligned)
constexpr int SM_RED = 18148;     // 16*25*2 = 800
constexpr int SMEM_FLOATS = 18948;
constexpr int SMEM_BYTES  = SMEM_FLOATS * 4;   // 75792 B -> 3 blocks/SM (227.4KB)

// ping-pong layer; A rows pre-duplicated u64; W/b from u64 constants
template<int FIN, int FOUT, int WOFF2, int BOFF2>
__device__ __forceinline__ void gcn_layer(const float* bIn, float* outRow, const u64* sA2row)
{
    constexpr int GP = (FIN >= 2) ? FIN/2 : 1;
    u64 g[GP];
    float g0 = 0.f;
    if (FIN == 1){
        const float* af = reinterpret_cast<const float*>(sA2row);
        #pragma unroll 8
        for (int j = 0; j < 24; j++) g0 += af[2*j] * bIn[j*RS2];
    } else {
        #pragma unroll
        for (int k = 0; k < GP; k++) g[k] = 0ull;
        #pragma unroll 4
        for (int j = 0; j < 24; j++){
            u64 a2 = sA2row[j];                  // single LDS.64, pre-duplicated
            const float* row = bIn + j*RS2;
            #pragma unroll
            for (int q = 0; q < FIN/4; q++){
                V4 v; v.q = *reinterpret_cast<const uint4*>(row + 4*q);
                g[2*q]   = fma2(a2, v.d[0], g[2*q]);
                g[2*q+1] = fma2(a2, v.d[1], g[2*q+1]);
            }
        }
    }

    constexpr int KP = FOUT/2;
    u64 acc[KP];
    #pragma unroll
    for (int k = 0; k < KP; k++) acc[k] = c_B2[BOFF2 + k];
    #pragma unroll
    for (int fi = 0; fi < FIN; fi++){
        float gs;
        if (FIN == 1) gs = g0;
        else { float lo, hi; upk2(g[fi/2], lo, hi); gs = (fi & 1) ? hi : lo; }
        u64 d = dup2(gs);
        #pragma unroll
        for (int k = 0; k < KP; k++)
            acc[k] = fma2(d, c_W2[WOFF2 + fi*KP + k], acc[k]);
    }
    #pragma unroll
    for (int k = 0; k < KP; k += 2){
        float a,b,c,dd;
        upk2(acc[k], a, b); upk2(acc[k+1], c, dd);
        V4 o;
        o.d[0] = pk2(fmaxf(a,0.f), fmaxf(b,0.f));
        o.d[1] = pk2(fmaxf(c,0.f), fmaxf(dd,0.f));
        *reinterpret_cast<uint4*>(outRow + 2*k) = o.q;
    }
    __syncthreads();
}

__global__ __launch_bounds__(NT, 3)
void gcn_fused_kernel(const float* __restrict__ x, float* __restrict__ out)
{
    extern __shared__ float sm[];
    float* bufA = sm + SM_BA;
    float* bufB = sm + SM_BB;
    float* sWc  = sm + SM_WC;
    u64*   sA2  = reinterpret_cast<u64*>(sm + SM_A2);
    float* sRed = sm + SM_RED;

    const int t = threadIdx.x;

    for (int i = t; i < 1586; i += NT) sWc[i] = g_wc[i];
    for (int i = t; i < 576; i += NT){
        float a = g_adj[i];
        sA2[(i/24)*25 + (i%24)] = dup2(a);
    }

    const int b_local = t / 24;
    const int node    = t % 24;
    const float* inA = bufA + b_local * BST2;
    const float* inB = bufB + b_local * BST2;
    float* rowA = bufA + b_local * BST2 + node * RS2;
    float* rowB = bufB + b_local * BST2 + node * RS2;
    const u64* sA2row = sA2 + node * 25;

    rowA[0] = x[blockIdx.x * (TB*24) + t];
    __syncthreads();

    gcn_layer< 1,  4,   0,  0>(inA, rowB, sA2row);
    gcn_layer< 4,  4,   2,  2>(inB, rowA, sA2row);
    gcn_layer< 4,  8,  10,  4>(inA, rowB, sA2row);
    gcn_layer< 8,  8,  26,  8>(inB, rowA, sA2row);
    gcn_layer< 8, 16,  58, 12>(inA, rowB, sA2row);
    gcn_layer<16, 16, 122, 20>(inB, rowA, sA2row);

    // ---- layer 7 (16->32) fused with folded FC head (reads bufA, regs only) ----
    u64 g[8];
    #pragma unroll
    for (int k = 0; k < 8; k++) g[k] = 0ull;
    #pragma unroll 4
    for (int j = 0; j < 24; j++){
        u64 a2 = sA2row[j];
        const float* row = inA + j*RS2;
        #pragma unroll
        for (int q = 0; q < 4; q++){
            V4 v; v.q = *reinterpret_cast<const uint4*>(row + 4*q);
            g[2*q]   = fma2(a2, v.d[0], g[2*q]);
            g[2*q+1] = fma2(a2, v.d[1], g[2*q+1]);
        }
    }
    u64 z = 0ull;
    const float* wcn = sWc + node * 66;
    #pragma unroll
    for (int pass = 0; pass < 2; pass++){
        u64 acc[8];
        #pragma unroll
        for (int k = 0; k < 8; k++) acc[k] = c_B2[28 + pass*8 + k];
        #pragma unroll
        for (int fi = 0; fi < 16; fi++){
            float lo, hi; upk2(g[fi/2], lo, hi);
            u64 d = dup2((fi & 1) ? hi : lo);
            #pragma unroll
            for (int k = 0; k < 8; k++)
                acc[k] = fma2(d, c_W2[250 + fi*16 + pass*8 + k], acc[k]);
        }
        const float* wcp = wcn + pass * 32;
        #pragma unroll
        for (int k = 0; k < 8; k++){
            float a, b; upk2(acc[k], a, b);
            z = fma2(dup2(fmaxf(a, 0.f)), lds2(wcp + 4*k),     z);
            z = fma2(dup2(fmaxf(b, 0.f)), lds2(wcp + 4*k + 2), z);
        }
    }
    *reinterpret_cast<u64*>(sRed + (b_local*25 + node)*2) = z;
    __syncthreads();

    if (t < TB){
        u64 s = lds2(sWc + 1584);   // bc
        const float* rb = sRed + t * 50;
        #pragma unroll 8
        for (int j = 0; j < 24; j++) s = add2(s, lds2(rb + 2*j));
        float z0, z1; upk2(s, z0, z1);
        float m = fmaxf(z0, z1);
        float lse = m + logf(expf(z0 - m) + expf(z1 - m));
        int gb = blockIdx.x * TB + t;
        out[gb*2 + 0] = z0 - lse;
        out[gb*2 + 1] = z1 - lse;
    }
}

extern "C" void kernel_launch(void* const* d_in, const int* in_sizes, int n_in,
                              void* d_out, int out_size)
{
    const float* x    = (const float*)d_in[0];
    const int*   ei   = (const int*)d_in[1];
    const float* fcw1 = (const float*)d_in[16];
    const float* fcb1 = (const float*)d_in[17];
    const float* fcw2 = (const float*)d_in[18];
    const float* fcb2 = (const float*)d_in[19];
    float* out = (float*)d_out;

    static const int woff[7] = {0, 4, 20, 52, 116, 244, 500};   // float offsets
    static const int wsz [7] = {4, 16, 32, 64, 128, 256, 512};
    static const int boff[7] = {0, 4, 8, 16, 24, 40, 56};
    static const int bsz [7] = {4, 4, 8, 8, 16, 16, 32};
    for (int i = 0; i < 7; i++){
        cudaMemcpyToSymbolAsync(c_W2, d_in[2 + 2*i], wsz[i]*4, woff[i]*4,
                                cudaMemcpyDeviceToDevice, 0);
        cudaMemcpyToSymbolAsync(c_B2, d_in[3 + 2*i], bsz[i]*4, boff[i]*4,
                                cudaMemcpyDeviceToDevice, 0);
    }

    const int B = in_sizes[0] / 24;
    const int grid = B / TB;

    cudaFuncSetAttribute(gcn_fused_kernel,
                         cudaFuncAttributeMaxDynamicSharedMemorySize, SMEM_BYTES);

    prologue_kernel<<<1, 768>>>(ei, fcw1, fcb1, fcw2, fcb2);
    gcn_fused_kernel<<<grid, NT, SMEM_BYTES>>>(x, out);
}

// round 9
// speedup vs baseline: 1.0392x; 1.0392x over previous
#include <cuda_runtime.h>
#include <math.h>

typedef unsigned long long u64;

__device__ __forceinline__ u64 dup2(float v){
    u64 r; asm("mov.b64 %0, {%1, %1};" : "=l"(r) : "f"(v)); return r;
}
__device__ __forceinline__ u64 pk2(float lo, float hi){
    u64 r; asm("mov.b64 %0, {%1, %2};" : "=l"(r) : "f"(lo), "f"(hi)); return r;
}
__device__ __forceinline__ void upk2(u64 a, float &lo, float &hi){
    asm("mov.b64 {%0, %1}, %2;" : "=f"(lo), "=f"(hi) : "l"(a));
}
__device__ __forceinline__ u64 fma2(u64 a, u64 b, u64 c){
    u64 d; asm("fma.rn.f32x2 %0, %1, %2, %3;" : "=l"(d) : "l"(a), "l"(b), "l"(c)); return d;
}
__device__ __forceinline__ u64 add2(u64 a, u64 b){
    u64 c; asm("add.rn.f32x2 %0, %1, %2;" : "=l"(c) : "l"(a), "l"(b)); return c;
}
__device__ __forceinline__ u64 lds2(const float* p){ return *reinterpret_cast<const u64*>(p); }

union V4 { uint4 q; u64 d[2]; };

// ---------- one fused constant bank: W (u64 0..505) then b (u64 506..549) ----------
__constant__ u64 c_WB2[550];
#define CB_B 506

// ---------- device globals ----------
__device__ float g_adj[576];
__device__ float g_wc[1586];     // Wc padded: node stride 66, bc at [1584..1585]
__device__ float g_pack[1100];   // staging for c_WB2 (W: 0..1011, b: 1012..1099)

// ---------- merged prologue: adjacency + folded FC head + weight packing ----------
__global__ void prologue_kernel(const int* __restrict__ ei_raw,
                                const float* __restrict__ W1, const float* __restrict__ b1,
                                const float* __restrict__ W2, const float* __restrict__ b2,
                                const float* __restrict__ W3, const float* __restrict__ b3,
                                const float* __restrict__ W4, const float* __restrict__ b4,
                                const float* __restrict__ W5, const float* __restrict__ b5,
                                const float* __restrict__ W6, const float* __restrict__ b6,
                                const float* __restrict__ W7, const float* __restrict__ b7,
                                const float* __restrict__ fcw1, const float* __restrict__ fcb1,
                                const float* __restrict__ fcw2, const float* __restrict__ fcb2){
    __shared__ float sdeg[24], sdinv[24], sAl[576];
    __shared__ float sw2[256];
    __shared__ int ssrc[96], sdst[96];
    __shared__ int is64;
    int t = threadIdx.x;      // 768 threads

    // ---- pack weights/biases into g_pack ----
    if (t < 4)    g_pack[0    + t] = W1[t];
    if (t < 16)   g_pack[4    + t] = W2[t];
    if (t < 32)   g_pack[20   + t] = W3[t];
    if (t < 64)   g_pack[52   + t] = W4[t];
    if (t < 128)  g_pack[116  + t] = W5[t];
    if (t < 256)  g_pack[244  + t] = W6[t];
    if (t < 512)  g_pack[500  + t] = W7[t];
    if (t < 4)    g_pack[1012 + t] = b1[t];
    if (t < 4)    g_pack[1016 + t] = b2[t];
    if (t < 8)    g_pack[1020 + t] = b3[t];
    if (t < 8)    g_pack[1028 + t] = b4[t];
    if (t < 16)   g_pack[1036 + t] = b5[t];
    if (t < 16)   g_pack[1052 + t] = b6[t];
    if (t < 32)   g_pack[1068 + t] = b7[t];

    if (t == 0){
        int z = 1;
        #pragma unroll 1
        for (int i = 1; i < 192; i += 2) if (ei_raw[i] != 0){ z = 0; break; }
        is64 = z;
    }
    if (t < 24) sdeg[t] = 1.0f;
    if (t < 576) sAl[t] = 0.0f;
    if (t >= 576 && t < 768) sw2[(t - 576)] = fcw2[t - 576];
    if (t < 64) sw2[192 + t] = fcw2[192 + t];
    __syncthreads();
    if (t < 96){
        int s, d;
        if (is64){
            const long long* e = reinterpret_cast<const long long*>(ei_raw);
            s = (int)e[t]; d = (int)e[96 + t];
        } else { s = ei_raw[t]; d = ei_raw[96 + t]; }
        s = min(max(s,0),23); d = min(max(d,0),23);
        ssrc[t] = s; sdst[t] = d;
        atomicAdd(&sdeg[d], 1.0f);
    }
    __syncthreads();
    if (t < 24) sdinv[t] = 1.0f / sqrtf(sdeg[t]);
    __syncthreads();
    if (t < 96) atomicAdd(&sAl[sdst[t]*24 + ssrc[t]], sdinv[ssrc[t]]*sdinv[sdst[t]]);
    if (t < 24) atomicAdd(&sAl[t*24 + t], sdinv[t]*sdinv[t]);
    __syncthreads();
    if (t < 576) g_adj[t] = sAl[t];

    // ---- Wc = fcw1 @ fcw2 (padded), bc = fcb1 @ fcw2 + fcb2 ----
    {
        float a0 = 0.f, a1 = 0.f;
        const float* row = fcw1 + t * 128;
        #pragma unroll 8
        for (int k = 0; k < 128; k++){
            float w = row[k];
            a0 += w * sw2[2*k];
            a1 += w * sw2[2*k + 1];
        }
        int node = t >> 5, fi = t & 31;
        g_wc[node*66 + 2*fi]     = a0;
        g_wc[node*66 + 2*fi + 1] = a1;
        if (t < 2){
            float b = fcb2[t];
            #pragma unroll 8
            for (int k = 0; k < 128; k++) b += fcb1[k] * sw2[2*k + t];
            g_wc[1584 + t] = b;
        }
    }
}

// ---------- fused GCN kernel ----------
#define NT 384
#define TB 16
#define RS2 20
#define BST2 (24*RS2)

constexpr int SM_BA  = 0;         // bufA: 7680 floats
constexpr int SM_BB  = 7680;      // bufB: 7680
constexpr int SM_WC  = 15360;     // 1586
constexpr int SM_A2  = 16948;     // A pre-dup'd u64: 1200 floats
constexpr int SM_RED = 18148;     // 800
constexpr int SMEM_FLOATS = 18948;
constexpr int SMEM_BYTES  = SMEM_FLOATS * 4;   // 75792 B -> 3 blocks/SM

template<int FIN, int FOUT, int WOFF2, int BOFF2>
__device__ __forceinline__ void gcn_layer(const float* bIn, float* outRow, const u64* sA2row)
{
    constexpr int GP = (FIN >= 2) ? FIN/2 : 1;
    u64 g[GP];
    float g0 = 0.f;
    if (FIN == 1){
        const float* af = reinterpret_cast<const float*>(sA2row);
        #pragma unroll 8
        for (int j = 0; j < 24; j++) g0 += af[2*j] * bIn[j*RS2];
    } else {
        #pragma unroll
        for (int k = 0; k < GP; k++) g[k] = 0ull;
        #pragma unroll 4
        for (int j = 0; j < 24; j++){
            u64 a2 = sA2row[j];
            const float* row = bIn + j*RS2;
            #pragma unroll
            for (int q = 0; q < FIN/4; q++){
                V4 v; v.q = *reinterpret_cast<const uint4*>(row + 4*q);
                g[2*q]   = fma2(a2, v.d[0], g[2*q]);
                g[2*q+1] = fma2(a2, v.d[1], g[2*q+1]);
            }
        }
    }

    constexpr int KP = FOUT/2;
    u64 acc[KP];
    #pragma unroll
    for (int k = 0; k < KP; k++) acc[k] = c_WB2[CB_B + BOFF2 + k];
    #pragma unroll
    for (int fi = 0; fi < FIN; fi++){
        float gs;
        if (FIN == 1) gs = g0;
        else { float lo, hi; upk2(g[fi/2], lo, hi); gs = (fi & 1) ? hi : lo; }
        u64 d = dup2(gs);
        #pragma unroll
        for (int k = 0; k < KP; k++)
            acc[k] = fma2(d, c_WB2[WOFF2 + fi*KP + k], acc[k]);
    }
    #pragma unroll
    for (int k = 0; k < KP; k += 2){
        float a,b,c,dd;
        upk2(acc[k], a, b); upk2(acc[k+1], c, dd);
        V4 o;
        o.d[0] = pk2(fmaxf(a,0.f), fmaxf(b,0.f));
        o.d[1] = pk2(fmaxf(c,0.f), fmaxf(dd,0.f));
        *reinterpret_cast<uint4*>(outRow + 2*k) = o.q;
    }
    __syncthreads();
}

__global__ __launch_bounds__(NT, 3)
void gcn_fused_kernel(const float* __restrict__ x, float* __restrict__ out)
{
    extern __shared__ float sm[];
    float* bufA = sm + SM_BA;
    float* bufB = sm + SM_BB;
    float* sWc  = sm + SM_WC;
    u64*   sA2  = reinterpret_cast<u64*>(sm + SM_A2);
    float* sRed = sm + SM_RED;

    const int t = threadIdx.x;

    for (int i = t; i < 1586; i += NT) sWc[i] = g_wc[i];
    for (int i = t; i < 576; i += NT){
        float a = g_adj[i];
        sA2[(i/24)*25 + (i%24)] = dup2(a);
    }

    const int b_local = t / 24;
    const int node    = t % 24;
    const float* inA = bufA + b_local * BST2;
    const float* inB = bufB + b_local * BST2;
    float* rowA = bufA + b_local * BST2 + node * RS2;
    float* rowB = bufB + b_local * BST2 + node * RS2;
    const u64* sA2row = sA2 + node * 25;

    rowA[0] = x[blockIdx.x * (TB*24) + t];
    __syncthreads();

    gcn_layer< 1,  4,   0,  0>(inA, rowB, sA2row);
    gcn_layer< 4,  4,   2,  2>(inB, rowA, sA2row);
    gcn_layer< 4,  8,  10,  4>(inA, rowB, sA2row);
    gcn_layer< 8,  8,  26,  8>(inB, rowA, sA2row);
    gcn_layer< 8, 16,  58, 12>(inA, rowB, sA2row);
    gcn_layer<16, 16, 122, 20>(inB, rowA, sA2row);

    // ---- layer 7 (16->32) fused with folded FC head ----
    u64 g[8];
    #pragma unroll
    for (int k = 0; k < 8; k++) g[k] = 0ull;
    #pragma unroll 4
    for (int j = 0; j < 24; j++){
        u64 a2 = sA2row[j];
        const float* row = inA + j*RS2;
        #pragma unroll
        for (int q = 0; q < 4; q++){
            V4 v; v.q = *reinterpret_cast<const uint4*>(row + 4*q);
            g[2*q]   = fma2(a2, v.d[0], g[2*q]);
            g[2*q+1] = fma2(a2, v.d[1], g[2*q+1]);
        }
    }
    u64 z = 0ull;
    const float* wcn = sWc + node * 66;
    #pragma unroll
    for (int pass = 0; pass < 2; pass++){
        u64 acc[8];
        #pragma unroll
        for (int k = 0; k < 8; k++) acc[k] = c_WB2[CB_B + 28 + pass*8 + k];
        #pragma unroll
        for (int fi = 0; fi < 16; fi++){
            float lo, hi; upk2(g[fi/2], lo, hi);
            u64 d = dup2((fi & 1) ? hi : lo);
            #pragma unroll
            for (int k = 0; k < 8; k++)
                acc[k] = fma2(d, c_WB2[250 + fi*16 + pass*8 + k], acc[k]);
        }
        const float* wcp = wcn + pass * 32;
        #pragma unroll
        for (int k = 0; k < 8; k++){
            float a, b; upk2(acc[k], a, b);
            z = fma2(dup2(fmaxf(a, 0.f)), lds2(wcp + 4*k),     z);
            z = fma2(dup2(fmaxf(b, 0.f)), lds2(wcp + 4*k + 2), z);
        }
    }
    *reinterpret_cast<u64*>(sRed + (b_local*25 + node)*2) = z;
    __syncthreads();

    if (t < TB){
        u64 s = lds2(sWc + 1584);   // bc
        const float* rb = sRed + t * 50;
        #pragma unroll 8
        for (int j = 0; j < 24; j++) s = add2(s, lds2(rb + 2*j));
        float z0, z1; upk2(s, z0, z1);
        float m = fmaxf(z0, z1);
        float lse = m + logf(expf(z0 - m) + expf(z1 - m));
        int gb = blockIdx.x * TB + t;
        out[gb*2 + 0] = z0 - lse;
        out[gb*2 + 1] = z1 - lse;
    }
}

extern "C" void kernel_launch(void* const* d_in, const int* in_sizes, int n_in,
                              void* d_out, int out_size)
{
    const float* x  = (const float*)d_in[0];
    const int*   ei = (const int*)d_in[1];
    float* out = (float*)d_out;

    const int B = in_sizes[0] / 24;
    const int grid = B / TB;

    cudaFuncSetAttribute(gcn_fused_kernel,
                         cudaFuncAttributeMaxDynamicSharedMemorySize, SMEM_BYTES);

    prologue_kernel<<<1, 768>>>(ei,
        (const float*)d_in[2],  (const float*)d_in[3],
        (const float*)d_in[4],  (const float*)d_in[5],
        (const float*)d_in[6],  (const float*)d_in[7],
        (const float*)d_in[8],  (const float*)d_in[9],
        (const float*)d_in[10], (const float*)d_in[11],
        (const float*)d_in[12], (const float*)d_in[13],
        (const float*)d_in[14], (const float*)d_in[15],
        (const float*)d_in[16], (const float*)d_in[17],
        (const float*)d_in[18], (const float*)d_in[19]);

    // single memcpy node: packed W/b -> constant bank
    void* packAddr = nullptr;
    cudaGetSymbolAddress(&packAddr, g_pack);
    cudaMemcpyToSymbolAsync(c_WB2, packAddr, 1100*4, 0,
                            cudaMemcpyDeviceToDevice, 0);

    gcn_fused_kernel<<<grid, NT, SMEM_BYTES>>>(x, out);
}

// round 10
// speedup vs baseline: 1.2620x; 1.2143x over previous
#include <cuda_runtime.h>
#include <math.h>

typedef unsigned long long u64;

__device__ __forceinline__ u64 dup2(float v){
    u64 r; asm("mov.b64 %0, {%1, %1};" : "=l"(r) : "f"(v)); return r;
}
__device__ __forceinline__ u64 pk2(float lo, float hi){
    u64 r; asm("mov.b64 %0, {%1, %2};" : "=l"(r) : "f"(lo), "f"(hi)); return r;
}
__device__ __forceinline__ void upk2(u64 a, float &lo, float &hi){
    asm("mov.b64 {%0, %1}, %2;" : "=f"(lo), "=f"(hi) : "l"(a));
}
__device__ __forceinline__ u64 fma2(u64 a, u64 b, u64 c){
    u64 d; asm("fma.rn.f32x2 %0, %1, %2, %3;" : "=l"(d) : "l"(a), "l"(b), "l"(c)); return d;
}
__device__ __forceinline__ u64 add2(u64 a, u64 b){
    u64 c; asm("add.rn.f32x2 %0, %1, %2;" : "=l"(c) : "l"(a), "l"(b)); return c;
}
__device__ __forceinline__ u64 lds2(const float* p){ return *reinterpret_cast<const u64*>(p); }

union V4 { uint4 q; u64 d[2]; };

// ---------- one fused constant bank: W (u64 0..505) then b (u64 506..549) ----------
__constant__ u64 c_WB2[550];
#define CB_B 506

// ---------- device globals ----------
__device__ float g_wc[1586];     // Wc padded: node stride 66, bc at [1584..1585]
__device__ float g_pack[1100];   // staging for c_WB2
__device__ u64   g_csr[576];     // per node: up to 24 (a,byteoff) entries, stride 24
__device__ int   g_maxn;

#define RS2 20                    // ping-pong row stride (floats)

// ---------- merged prologue ----------
__global__ void prologue_kernel(const int* __restrict__ ei_raw,
                                const float* __restrict__ W1, const float* __restrict__ b1,
                                const float* __restrict__ W2, const float* __restrict__ b2,
                                const float* __restrict__ W3, const float* __restrict__ b3,
                                const float* __restrict__ W4, const float* __restrict__ b4,
                                const float* __restrict__ W5, const float* __restrict__ b5,
                                const float* __restrict__ W6, const float* __restrict__ b6,
                                const float* __restrict__ W7, const float* __restrict__ b7,
                                const float* __restrict__ fcw1, const float* __restrict__ fcb1,
                                const float* __restrict__ fcw2, const float* __restrict__ fcb2){
    __shared__ float sdeg[24], sdinv[24], sAl[576];
    __shared__ float sw2[256];
    __shared__ int ssrc[96], sdst[96];
    __shared__ int is64, scnt[24], smax;
    int t = threadIdx.x;      // 768 threads

    // ---- pack weights/biases into g_pack ----
    if (t < 4)    g_pack[0    + t] = W1[t];
    if (t < 16)   g_pack[4    + t] = W2[t];
    if (t < 32)   g_pack[20   + t] = W3[t];
    if (t < 64)   g_pack[52   + t] = W4[t];
    if (t < 128)  g_pack[116  + t] = W5[t];
    if (t < 256)  g_pack[244  + t] = W6[t];
    if (t < 512)  g_pack[500  + t] = W7[t];
    if (t < 4)    g_pack[1012 + t] = b1[t];
    if (t < 4)    g_pack[1016 + t] = b2[t];
    if (t < 8)    g_pack[1020 + t] = b3[t];
    if (t < 8)    g_pack[1028 + t] = b4[t];
    if (t < 16)   g_pack[1036 + t] = b5[t];
    if (t < 16)   g_pack[1052 + t] = b6[t];
    if (t < 32)   g_pack[1068 + t] = b7[t];

    if (t == 0){
        int z = 1;
        #pragma unroll 1
        for (int i = 1; i < 192; i += 2) if (ei_raw[i] != 0){ z = 0; break; }
        is64 = z;
        smax = 0;
    }
    if (t < 24) sdeg[t] = 1.0f;
    if (t < 576) sAl[t] = 0.0f;
    if (t >= 576 && t < 768) sw2[(t - 576)] = fcw2[t - 576];
    if (t < 64) sw2[192 + t] = fcw2[192 + t];
    __syncthreads();
    if (t < 96){
        int s, d;
        if (is64){
            const long long* e = reinterpret_cast<const long long*>(ei_raw);
            s = (int)e[t]; d = (int)e[96 + t];
        } else { s = ei_raw[t]; d = ei_raw[96 + t]; }
        s = min(max(s,0),23); d = min(max(d,0),23);
        ssrc[t] = s; sdst[t] = d;
        atomicAdd(&sdeg[d], 1.0f);
    }
    __syncthreads();
    if (t < 24) sdinv[t] = 1.0f / sqrtf(sdeg[t]);
    __syncthreads();
    if (t < 96) atomicAdd(&sAl[sdst[t]*24 + ssrc[t]], sdinv[ssrc[t]]*sdinv[sdst[t]]);
    if (t < 24) atomicAdd(&sAl[t*24 + t], sdinv[t]*sdinv[t]);
    __syncthreads();

    // ---- CSR compaction of A rows (nonzeros only, padded later) ----
    if (t < 24){
        int c = 0;
        #pragma unroll 1
        for (int j = 0; j < 24; j++){
            float a = sAl[t*24 + j];
            if (a != 0.0f){
                u64 e = ((u64)__float_as_uint(a) << 32) | (u64)(unsigned)(j * RS2 * 4);
                g_csr[t*24 + c] = e;
                c++;
            }
        }
        scnt[t] = c;
        atomicMax(&smax, c);
    }
    __syncthreads();
    if (t < 24){
        for (int k = scnt[t]; k < smax; k++) g_csr[t*24 + k] = 0ull;  // a=0, off=0
    }
    if (t == 0) g_maxn = smax;

    // ---- Wc = fcw1 @ fcw2 (padded), bc = fcb1 @ fcw2 + fcb2 ----
    {
        float a0 = 0.f, a1 = 0.f;
        const float* row = fcw1 + t * 128;
        #pragma unroll 8
        for (int k = 0; k < 128; k++){
            float w = row[k];
            a0 += w * sw2[2*k];
            a1 += w * sw2[2*k + 1];
        }
        int node = t >> 5, fi = t & 31;
        g_wc[node*66 + 2*fi]     = a0;
        g_wc[node*66 + 2*fi + 1] = a1;
        if (t < 2){
            float b = fcb2[t];
            #pragma unroll 8
            for (int k = 0; k < 128; k++) b += fcb1[k] * sw2[2*k + t];
            g_wc[1584 + t] = b;
        }
    }
}

// ---------- fused GCN kernel ----------
#define NT 384
#define TB 16
#define BST2 (24*RS2)

constexpr int SM_BA  = 0;         // bufA: 7680 floats
constexpr int SM_BB  = 7680;      // bufB: 7680
constexpr int SM_WC  = 15360;     // 1586
constexpr int SM_CSR = 16948;     // u64[24*25] = 1200 floats (stride 25: bank-spread)
constexpr int SM_RED = 18148;     // 800
constexpr int SM_MX  = 18948;     // 1 int
constexpr int SMEM_FLOATS = 18952;
constexpr int SMEM_BYTES  = SMEM_FLOATS * 4;   // 75808 B -> 3 blocks/SM

// sparse-aggregate layer: g = Σ_k a_k * bIn[off_k], out = relu(g.W + b)
template<int FIN, int FOUT, int WOFF2, int BOFF2>
__device__ __forceinline__ void gcn_layer(const float* bIn, float* outRow,
                                          const u64* csrRow, int maxn)
{
    constexpr int GP = (FIN >= 2) ? FIN/2 : 1;
    u64 g[GP];
    float g0 = 0.f;
    if (FIN == 1){
        #pragma unroll 4
        for (int k = 0; k < maxn; k++){
            u64 e = csrRow[k];
            float a = __uint_as_float((unsigned)(e >> 32));
            const float* row = (const float*)((const char*)bIn + (unsigned)e);
            g0 += a * row[0];
        }
    } else {
        #pragma unroll
        for (int k = 0; k < GP; k++) g[k] = 0ull;
        #pragma unroll 4
        for (int k = 0; k < maxn; k++){
            u64 e = csrRow[k];
            u64 a2 = dup2(__uint_as_float((unsigned)(e >> 32)));
            const float* row = (const float*)((const char*)bIn + (unsigned)e);
            #pragma unroll
            for (int q = 0; q < FIN/4; q++){
                V4 v; v.q = *reinterpret_cast<const uint4*>(row + 4*q);
                g[2*q]   = fma2(a2, v.d[0], g[2*q]);
                g[2*q+1] = fma2(a2, v.d[1], g[2*q+1]);
            }
        }
    }

    constexpr int KP = FOUT/2;
    u64 acc[KP];
    #pragma unroll
    for (int k = 0; k < KP; k++) acc[k] = c_WB2[CB_B + BOFF2 + k];
    #pragma unroll
    for (int fi = 0; fi < FIN; fi++){
        float gs;
        if (FIN == 1) gs = g0;
        else { float lo, hi; upk2(g[fi/2], lo, hi); gs = (fi & 1) ? hi : lo; }
        u64 d = dup2(gs);
        #pragma unroll
        for (int k = 0; k < KP; k++)
            acc[k] = fma2(d, c_WB2[WOFF2 + fi*KP + k], acc[k]);
    }
    #pragma unroll
    for (int k = 0; k < KP; k += 2){
        float a,b,c,dd;
        upk2(acc[k], a, b); upk2(acc[k+1], c, dd);
        V4 o;
        o.d[0] = pk2(fmaxf(a,0.f), fmaxf(b,0.f));
        o.d[1] = pk2(fmaxf(c,0.f), fmaxf(dd,0.f));
        *reinterpret_cast<uint4*>(outRow + 2*k) = o.q;
    }
    __syncthreads();
}

__global__ __launch_bounds__(NT, 3)
void gcn_fused_kernel(const float* __restrict__ x, float* __restrict__ out)
{
    extern __shared__ float sm[];
    float* bufA = sm + SM_BA;
    float* bufB = sm + SM_BB;
    float* sWc  = sm + SM_WC;
    u64*   sCsr = reinterpret_cast<u64*>(sm + SM_CSR);
    float* sRed = sm + SM_RED;
    int*   sMx  = reinterpret_cast<int*>(sm + SM_MX);

    const int t = threadIdx.x;

    for (int i = t; i < 1586; i += NT) sWc[i] = g_wc[i];
    for (int i = t; i < 576; i += NT) sCsr[(i/24)*25 + (i%24)] = g_csr[i];
    if (t == 0) *sMx = g_maxn;

    const int b_local = t / 24;
    const int node    = t % 24;
    const float* inA = bufA + b_local * BST2;
    const float* inB = bufB + b_local * BST2;
    float* rowA = bufA + b_local * BST2 + node * RS2;
    float* rowB = bufB + b_local * BST2 + node * RS2;
    const u64* csrRow = sCsr + node * 25;

    rowA[0] = x[blockIdx.x * (TB*24) + t];
    __syncthreads();
    const int maxn = *sMx;

    gcn_layer< 1,  4,   0,  0>(inA, rowB, csrRow, maxn);
    gcn_layer< 4,  4,   2,  2>(inB, rowA, csrRow, maxn);
    gcn_layer< 4,  8,  10,  4>(inA, rowB, csrRow, maxn);
    gcn_layer< 8,  8,  26,  8>(inB, rowA, csrRow, maxn);
    gcn_layer< 8, 16,  58, 12>(inA, rowB, csrRow, maxn);
    gcn_layer<16, 16, 122, 20>(inB, rowA, csrRow, maxn);

    // ---- layer 7 (16->32) fused with folded FC head (reads bufA, regs only) ----
    u64 g[8];
    #pragma unroll
    for (int k = 0; k < 8; k++) g[k] = 0ull;
    #pragma unroll 4
    for (int k = 0; k < maxn; k++){
        u64 e = csrRow[k];
        u64 a2 = dup2(__uint_as_float((unsigned)(e >> 32)));
        const float* row = (const float*)((const char*)inA + (unsigned)e);
        #pragma unroll
        for (int q = 0; q < 4; q++){
            V4 v; v.q = *reinterpret_cast<const uint4*>(row + 4*q);
            g[2*q]   = fma2(a2, v.d[0], g[2*q]);
            g[2*q+1] = fma2(a2, v.d[1], g[2*q+1]);
        }
    }
    u64 z = 0ull;
    const float* wcn = sWc + node * 66;
    #pragma unroll
    for (int pass = 0; pass < 2; pass++){
        u64 acc[8];
        #pragma unroll
        for (int k = 0; k < 8; k++) acc[k] = c_WB2[CB_B + 28 + pass*8 + k];
        #pragma unroll
        for (int fi = 0; fi < 16; fi++){
            float lo, hi; upk2(g[fi/2], lo, hi);
            u64 d = dup2((fi & 1) ? hi : lo);
            #pragma unroll
            for (int k = 0; k < 8; k++)
                acc[k] = fma2(d, c_WB2[250 + fi*16 + pass*8 + k], acc[k]);
        }
        const float* wcp = wcn + pass * 32;
        #pragma unroll
        for (int k = 0; k < 8; k++){
            float a, b; upk2(acc[k], a, b);
            z = fma2(dup2(fmaxf(a, 0.f)), lds2(wcp + 4*k),     z);
            z = fma2(dup2(fmaxf(b, 0.f)), lds2(wcp + 4*k + 2), z);
        }
    }
    *reinterpret_cast<u64*>(sRed + (b_local*25 + node)*2) = z;
    __syncthreads();

    if (t < TB){
        u64 s = lds2(sWc + 1584);   // bc
        const float* rb = sRed + t * 50;
        #pragma unroll 8
        for (int j = 0; j < 24; j++) s = add2(s, lds2(rb + 2*j));
        float z0, z1; upk2(s, z0, z1);
        float m = fmaxf(z0, z1);
        float lse = m + logf(expf(z0 - m) + expf(z1 - m));
        int gb = blockIdx.x * TB + t;
        out[gb*2 + 0] = z0 - lse;
        out[gb*2 + 1] = z1 - lse;
    }
}

extern "C" void kernel_launch(void* const* d_in, const int* in_sizes, int n_in,
                              void* d_out, int out_size)
{
    const float* x  = (const float*)d_in[0];
    const int*   ei = (const int*)d_in[1];
    float* out = (float*)d_out;

    const int B = in_sizes[0] / 24;
    const int grid = B / TB;

    cudaFuncSetAttribute(gcn_fused_kernel,
                         cudaFuncAttributeMaxDynamicSharedMemorySize, SMEM_BYTES);

    prologue_kernel<<<1, 768>>>(ei,
        (const float*)d_in[2],  (const float*)d_in[3],
        (const float*)d_in[4],  (const float*)d_in[5],
        (const float*)d_in[6],  (const float*)d_in[7],
        (const float*)d_in[8],  (const float*)d_in[9],
        (const float*)d_in[10], (const float*)d_in[11],
        (const float*)d_in[12], (const float*)d_in[13],
        (const float*)d_in[14], (const float*)d_in[15],
        (const float*)d_in[16], (const float*)d_in[17],
        (const float*)d_in[18], (const float*)d_in[19]);

    void* packAddr = nullptr;
    cudaGetSymbolAddress(&packAddr, g_pack);
    cudaMemcpyToSymbolAsync(c_WB2, packAddr, 1100*4, 0,
                            cudaMemcpyDeviceToDevice, 0);

    gcn_fused_kernel<<<grid, NT, SMEM_BYTES>>>(x, out);
}

// round 11
// speedup vs baseline: 1.2778x; 1.0126x over previous
#include <cuda_runtime.h>
#include <math.h>

typedef unsigned long long u64;

__device__ __forceinline__ u64 dup2(float v){
    u64 r; asm("mov.b64 %0, {%1, %1};" : "=l"(r) : "f"(v)); return r;
}
__device__ __forceinline__ u64 pk2(float lo, float hi){
    u64 r; asm("mov.b64 %0, {%1, %2};" : "=l"(r) : "f"(lo), "f"(hi)); return r;
}
__device__ __forceinline__ void upk2(u64 a, float &lo, float &hi){
    asm("mov.b64 {%0, %1}, %2;" : "=f"(lo), "=f"(hi) : "l"(a));
}
__device__ __forceinline__ u64 fma2(u64 a, u64 b, u64 c){
    u64 d; asm("fma.rn.f32x2 %0, %1, %2, %3;" : "=l"(d) : "l"(a), "l"(b), "l"(c)); return d;
}
__device__ __forceinline__ u64 add2(u64 a, u64 b){
    u64 c; asm("add.rn.f32x2 %0, %1, %2;" : "=l"(c) : "l"(a), "l"(b)); return c;
}
__device__ __forceinline__ u64 lds2(const float* p){ return *reinterpret_cast<const u64*>(p); }
__device__ __forceinline__ void gbar(int id){
    asm volatile("bar.sync %0, 96;" :: "r"(id) : "memory");
}

union V4 { uint4 q; u64 d[2]; };

// ---------- one fused constant bank: W (u64 0..505) then b (u64 506..549) ----------
__constant__ u64 c_WB2[550];
#define CB_B 506

// ---------- device globals ----------
__device__ float g_wc[1586];     // Wc padded: node stride 66, bc at [1584..1585]
__device__ float g_pack[1100];   // staging for c_WB2
__device__ u64   g_csr[576];     // per node: up to 24 (a,byteoff) entries, stride 24
__device__ int   g_maxn;

#define RS2 20                    // ping-pong row stride (floats)

// ---------- merged prologue ----------
__global__ void prologue_kernel(const int* __restrict__ ei_raw,
                                const float* __restrict__ W1, const float* __restrict__ b1,
                                const float* __restrict__ W2, const float* __restrict__ b2,
                                const float* __restrict__ W3, const float* __restrict__ b3,
                                const float* __restrict__ W4, const float* __restrict__ b4,
                                const float* __restrict__ W5, const float* __restrict__ b5,
                                const float* __restrict__ W6, const float* __restrict__ b6,
                                const float* __restrict__ W7, const float* __restrict__ b7,
                                const float* __restrict__ fcw1, const float* __restrict__ fcb1,
                                const float* __restrict__ fcw2, const float* __restrict__ fcb2){
    __shared__ float sdeg[24], sdinv[24], sAl[576];
    __shared__ float sw2[256];
    __shared__ int ssrc[96], sdst[96];
    __shared__ int is64, scnt[24], smax;
    int t = threadIdx.x;      // 768 threads

    if (t < 4)    g_pack[0    + t] = W1[t];
    if (t < 16)   g_pack[4    + t] = W2[t];
    if (t < 32)   g_pack[20   + t] = W3[t];
    if (t < 64)   g_pack[52   + t] = W4[t];
    if (t < 128)  g_pack[116  + t] = W5[t];
    if (t < 256)  g_pack[244  + t] = W6[t];
    if (t < 512)  g_pack[500  + t] = W7[t];
    if (t < 4)    g_pack[1012 + t] = b1[t];
    if (t < 4)    g_pack[1016 + t] = b2[t];
    if (t < 8)    g_pack[1020 + t] = b3[t];
    if (t < 8)    g_pack[1028 + t] = b4[t];
    if (t < 16)   g_pack[1036 + t] = b5[t];
    if (t < 16)   g_pack[1052 + t] = b6[t];
    if (t < 32)   g_pack[1068 + t] = b7[t];

    if (t == 0){
        int z = 1;
        #pragma unroll 1
        for (int i = 1; i < 192; i += 2) if (ei_raw[i] != 0){ z = 0; break; }
        is64 = z;
        smax = 0;
    }
    if (t < 24) sdeg[t] = 1.0f;
    if (t < 576) sAl[t] = 0.0f;
    if (t >= 576 && t < 768) sw2[(t - 576)] = fcw2[t - 576];
    if (t < 64) sw2[192 + t] = fcw2[192 + t];
    __syncthreads();
    if (t < 96){
        int s, d;
        if (is64){
            const long long* e = reinterpret_cast<const long long*>(ei_raw);
            s = (int)e[t]; d = (int)e[96 + t];
        } else { s = ei_raw[t]; d = ei_raw[96 + t]; }
        s = min(max(s,0),23); d = min(max(d,0),23);
        ssrc[t] = s; sdst[t] = d;
        atomicAdd(&sdeg[d], 1.0f);
    }
    __syncthreads();
    if (t < 24) sdinv[t] = 1.0f / sqrtf(sdeg[t]);
    __syncthreads();
    if (t < 96) atomicAdd(&sAl[sdst[t]*24 + ssrc[t]], sdinv[ssrc[t]]*sdinv[sdst[t]]);
    if (t < 24) atomicAdd(&sAl[t*24 + t], sdinv[t]*sdinv[t]);
    __syncthreads();

    // ---- CSR compaction ----
    if (t < 24){
        int c = 0;
        #pragma unroll 1
        for (int j = 0; j < 24; j++){
            float a = sAl[t*24 + j];
            if (a != 0.0f){
                u64 e = ((u64)__float_as_uint(a) << 32) | (u64)(unsigned)(j * RS2 * 4);
                g_csr[t*24 + c] = e;
                c++;
            }
        }
        scnt[t] = c;
        atomicMax(&smax, c);
    }
    __syncthreads();
    if (t < 24){
        for (int k = scnt[t]; k < smax; k++) g_csr[t*24 + k] = 0ull;
    }
    if (t == 0) g_maxn = smax;

    // ---- Wc = fcw1 @ fcw2 (padded), bc = fcb1 @ fcw2 + fcb2 ----
    {
        float a0 = 0.f, a1 = 0.f;
        const float* row = fcw1 + t * 128;
        #pragma unroll 8
        for (int k = 0; k < 128; k++){
            float w = row[k];
            a0 += w * sw2[2*k];
            a1 += w * sw2[2*k + 1];
        }
        int node = t >> 5, fi = t & 31;
        g_wc[node*66 + 2*fi]     = a0;
        g_wc[node*66 + 2*fi + 1] = a1;
        if (t < 2){
            float b = fcb2[t];
            #pragma unroll 8
            for (int k = 0; k < 128; k++) b += fcb1[k] * sw2[2*k + t];
            g_wc[1584 + t] = b;
        }
    }
}

// ---------- fused GCN kernel ----------
#define NT 384
#define TB 16
#define BST2 (24*RS2)

constexpr int SM_BA  = 0;         // bufA: 7680 floats
constexpr int SM_BB  = 7680;      // bufB: 7680
constexpr int SM_WC  = 15360;     // 1586
constexpr int SM_CSR = 16948;     // u64[24*25] = 1200 floats
constexpr int SM_RED = 18148;     // 800
constexpr int SM_MX  = 18948;     // 1 int
constexpr int SMEM_FLOATS = 18952;
constexpr int SMEM_BYTES  = SMEM_FLOATS * 4;   // 75808 B -> 3 blocks/SM

// sparse-aggregate layer; group-scoped barrier (96 threads)
template<int FIN, int FOUT, int WOFF2, int BOFF2>
__device__ __forceinline__ void gcn_layer(const float* bIn, float* outRow,
                                          const u64* csrRow, int maxn, int barid)
{
    constexpr int GP = (FIN >= 2) ? FIN/2 : 1;
    u64 g[GP];
    float g0 = 0.f;
    if (FIN == 1){
        #pragma unroll 4
        for (int k = 0; k < maxn; k++){
            u64 e = csrRow[k];
            float a = __uint_as_float((unsigned)(e >> 32));
            const float* row = (const float*)((const char*)bIn + (unsigned)e);
            g0 += a * row[0];
        }
    } else {
        #pragma unroll
        for (int k = 0; k < GP; k++) g[k] = 0ull;
        #pragma unroll 4
        for (int k = 0; k < maxn; k++){
            u64 e = csrRow[k];
            u64 a2 = dup2(__uint_as_float((unsigned)(e >> 32)));
            const float* row = (const float*)((const char*)bIn + (unsigned)e);
            #pragma unroll
            for (int q = 0; q < FIN/4; q++){
                V4 v; v.q = *reinterpret_cast<const uint4*>(row + 4*q);
                g[2*q]   = fma2(a2, v.d[0], g[2*q]);
                g[2*q+1] = fma2(a2, v.d[1], g[2*q+1]);
            }
        }
    }

    constexpr int KP = FOUT/2;
    u64 acc[KP];
    #pragma unroll
    for (int k = 0; k < KP; k++) acc[k] = c_WB2[CB_B + BOFF2 + k];
    #pragma unroll
    for (int fi = 0; fi < FIN; fi++){
        float gs;
        if (FIN == 1) gs = g0;
        else { float lo, hi; upk2(g[fi/2], lo, hi); gs = (fi & 1) ? hi : lo; }
        u64 d = dup2(gs);
        #pragma unroll
        for (int k = 0; k < KP; k++)
            acc[k] = fma2(d, c_WB2[WOFF2 + fi*KP + k], acc[k]);
    }
    #pragma unroll
    for (int k = 0; k < KP; k += 2){
        float a,b,c,dd;
        upk2(acc[k], a, b); upk2(acc[k+1], c, dd);
        V4 o;
        o.d[0] = pk2(fmaxf(a,0.f), fmaxf(b,0.f));
        o.d[1] = pk2(fmaxf(c,0.f), fmaxf(dd,0.f));
        *reinterpret_cast<uint4*>(outRow + 2*k) = o.q;
    }
    gbar(barid);
}

__global__ __launch_bounds__(NT, 3)
void gcn_fused_kernel(const float* __restrict__ x, float* __restrict__ out)
{
    extern __shared__ float sm[];
    float* bufA = sm + SM_BA;
    float* bufB = sm + SM_BB;
    float* sWc  = sm + SM_WC;
    u64*   sCsr = reinterpret_cast<u64*>(sm + SM_CSR);
    float* sRed = sm + SM_RED;
    int*   sMx  = reinterpret_cast<int*>(sm + SM_MX);

    const int t = threadIdx.x;
    const int grp = t / 96;            // 4 groups of 96 threads (3 warps each)
    const int barid = 1 + grp;

    for (int i = t; i < 1586; i += NT) sWc[i] = g_wc[i];
    for (int i = t; i < 576; i += NT) sCsr[(i/24)*25 + (i%24)] = g_csr[i];
    if (t == 0) *sMx = g_maxn;

    const int b_local = t / 24;
    const int node    = t % 24;
    const float* inA = bufA + b_local * BST2;
    const float* inB = bufB + b_local * BST2;
    float* rowA = bufA + b_local * BST2 + node * RS2;
    float* rowB = bufB + b_local * BST2 + node * RS2;
    const u64* csrRow = sCsr + node * 25;

    rowA[0] = x[blockIdx.x * (TB*24) + t];
    __syncthreads();                    // covers staging + x for all groups
    const int maxn = *sMx;

    gcn_layer< 1,  4,   0,  0>(inA, rowB, csrRow, maxn, barid);
    gcn_layer< 4,  4,   2,  2>(inB, rowA, csrRow, maxn, barid);
    gcn_layer< 4,  8,  10,  4>(inA, rowB, csrRow, maxn, barid);
    gcn_layer< 8,  8,  26,  8>(inB, rowA, csrRow, maxn, barid);
    gcn_layer< 8, 16,  58, 12>(inA, rowB, csrRow, maxn, barid);
    gcn_layer<16, 16, 122, 20>(inB, rowA, csrRow, maxn, barid);

    // ---- layer 7 (16->32) fused with folded FC head (reads bufA, regs only) ----
    u64 g[8];
    #pragma unroll
    for (int k = 0; k < 8; k++) g[k] = 0ull;
    #pragma unroll 4
    for (int k = 0; k < maxn; k++){
        u64 e = csrRow[k];
        u64 a2 = dup2(__uint_as_float((unsigned)(e >> 32)));
        const float* row = (const float*)((const char*)inA + (unsigned)e);
        #pragma unroll
        for (int q = 0; q < 4; q++){
            V4 v; v.q = *reinterpret_cast<const uint4*>(row + 4*q);
            g[2*q]   = fma2(a2, v.d[0], g[2*q]);
            g[2*q+1] = fma2(a2, v.d[1], g[2*q+1]);
        }
    }
    u64 z = 0ull;
    const float* wcn = sWc + node * 66;
    #pragma unroll
    for (int pass = 0; pass < 2; pass++){
        u64 acc[8];
        #pragma unroll
        for (int k = 0; k < 8; k++) acc[k] = c_WB2[CB_B + 28 + pass*8 + k];
        #pragma unroll
        for (int fi = 0; fi < 16; fi++){
            float lo, hi; upk2(g[fi/2], lo, hi);
            u64 d = dup2((fi & 1) ? hi : lo);
            #pragma unroll
            for (int k = 0; k < 8; k++)
                acc[k] = fma2(d, c_WB2[250 + fi*16 + pass*8 + k], acc[k]);
        }
        const float* wcp = wcn + pass * 32;
        #pragma unroll
        for (int k = 0; k < 8; k++){
            float a, b; upk2(acc[k], a, b);
            z = fma2(dup2(fmaxf(a, 0.f)), lds2(wcp + 4*k),     z);
            z = fma2(dup2(fmaxf(b, 0.f)), lds2(wcp + 4*k + 2), z);
        }
    }
    *reinterpret_cast<u64*>(sRed + (b_local*25 + node)*2) = z;
    gbar(barid);

    // ---- group-local reduce + log_softmax: first 4 threads of each group ----
    if (t % 96 < 4){
        int b = grp * 4 + (t % 96);     // batch within block
        u64 s = lds2(sWc + 1584);       // bc
        const float* rb = sRed + b * 50;
        #pragma unroll 8
        for (int j = 0; j < 24; j++) s = add2(s, lds2(rb + 2*j));
        float z0, z1; upk2(s, z0, z1);
        float m = fmaxf(z0, z1);
        float lse = m + logf(expf(z0 - m) + expf(z1 - m));
        int gb = blockIdx.x * TB + b;
        out[gb*2 + 0] = z0 - lse;
        out[gb*2 + 1] = z1 - lse;
    }
}

extern "C" void kernel_launch(void* const* d_in, const int* in_sizes, int n_in,
                              void* d_out, int out_size)
{
    const float* x  = (const float*)d_in[0];
    const int*   ei = (const int*)d_in[1];
    float* out = (float*)d_out;

    const int B = in_sizes[0] / 24;
    const int grid = B / TB;

    cudaFuncSetAttribute(gcn_fused_kernel,
                         cudaFuncAttributeMaxDynamicSharedMemorySize, SMEM_BYTES);

    prologue_kernel<<<1, 768>>>(ei,
        (const float*)d_in[2],  (const float*)d_in[3],
        (const float*)d_in[4],  (const float*)d_in[5],
        (const float*)d_in[6],  (const float*)d_in[7],
        (const float*)d_in[8],  (const float*)d_in[9],
        (const float*)d_in[10], (const float*)d_in[11],
        (const float*)d_in[12], (const float*)d_in[13],
        (const float*)d_in[14], (const float*)d_in[15],
        (const float*)d_in[16], (const float*)d_in[17],
        (const float*)d_in[18], (const float*)d_in[19]);

    void* packAddr = nullptr;
    cudaGetSymbolAddress(&packAddr, g_pack);
    cudaMemcpyToSymbolAsync(c_WB2, packAddr, 1100*4, 0,
                            cudaMemcpyDeviceToDevice, 0);

    gcn_fused_kernel<<<grid, NT, SMEM_BYTES>>>(x, out);
}

// round 12
// speedup vs baseline: 1.2855x; 1.0060x over previous
#include <cuda_runtime.h>
#include <math.h>

typedef unsigned long long u64;

__device__ __forceinline__ u64 dup2(float v){
    u64 r; asm("mov.b64 %0, {%1, %1};" : "=l"(r) : "f"(v)); return r;
}
__device__ __forceinline__ u64 pk2(float lo, float hi){
    u64 r; asm("mov.b64 %0, {%1, %2};" : "=l"(r) : "f"(lo), "f"(hi)); return r;
}
__device__ __forceinline__ void upk2(u64 a, float &lo, float &hi){
    asm("mov.b64 {%0, %1}, %2;" : "=f"(lo), "=f"(hi) : "l"(a));
}
__device__ __forceinline__ u64 fma2(u64 a, u64 b, u64 c){
    u64 d; asm("fma.rn.f32x2 %0, %1, %2, %3;" : "=l"(d) : "l"(a), "l"(b), "l"(c)); return d;
}
__device__ __forceinline__ u64 add2(u64 a, u64 b){
    u64 c; asm("add.rn.f32x2 %0, %1, %2;" : "=l"(c) : "l"(a), "l"(b)); return c;
}
__device__ __forceinline__ u64 lds2(const float* p){ return *reinterpret_cast<const u64*>(p); }
__device__ __forceinline__ u64 bfly64(u64 v, int m){
    unsigned lo = (unsigned)v, hi = (unsigned)(v >> 32);
    lo = __shfl_xor_sync(0xffffffffu, lo, m);
    hi = __shfl_xor_sync(0xffffffffu, hi, m);
    return ((u64)hi << 32) | (u64)lo;
}

// ---------- one fused constant bank: W (u64 0..505) then b (u64 506..549) ----------
__constant__ u64 c_WB2[550];
#define CB_B 506

// ---------- device globals ----------
__device__ float g_wc[1586];     // Wc padded: node stride 66, bc at [1584..1585]
__device__ float g_pack[1100];   // staging for c_WB2
__device__ u64   g_csr[384];     // 24 nodes x 16 entries: (f32 a)<<32 | src_node
__device__ int   g_maxn;

// ---------- merged prologue ----------
__global__ void prologue_kernel(const int* __restrict__ ei_raw,
                                const float* __restrict__ W1, const float* __restrict__ b1,
                                const float* __restrict__ W2, const float* __restrict__ b2,
                                const float* __restrict__ W3, const float* __restrict__ b3,
                                const float* __restrict__ W4, const float* __restrict__ b4,
                                const float* __restrict__ W5, const float* __restrict__ b5,
                                const float* __restrict__ W6, const float* __restrict__ b6,
                                const float* __restrict__ W7, const float* __restrict__ b7,
                                const float* __restrict__ fcw1, const float* __restrict__ fcb1,
                                const float* __restrict__ fcw2, const float* __restrict__ fcb2){
    __shared__ float sdeg[24], sdinv[24], sAl[576];
    __shared__ float sw2[256];
    __shared__ int ssrc[96], sdst[96];
    __shared__ int is64, scnt[24], smax;
    int t = threadIdx.x;      // 768 threads

    if (t < 4)    g_pack[0    + t] = W1[t];
    if (t < 16)   g_pack[4    + t] = W2[t];
    if (t < 32)   g_pack[20   + t] = W3[t];
    if (t < 64)   g_pack[52   + t] = W4[t];
    if (t < 128)  g_pack[116  + t] = W5[t];
    if (t < 256)  g_pack[244  + t] = W6[t];
    if (t < 512)  g_pack[500  + t] = W7[t];
    if (t < 4)    g_pack[1012 + t] = b1[t];
    if (t < 4)    g_pack[1016 + t] = b2[t];
    if (t < 8)    g_pack[1020 + t] = b3[t];
    if (t < 8)    g_pack[1028 + t] = b4[t];
    if (t < 16)   g_pack[1036 + t] = b5[t];
    if (t < 16)   g_pack[1052 + t] = b6[t];
    if (t < 32)   g_pack[1068 + t] = b7[t];

    if (t == 0){
        int z = 1;
        #pragma unroll 1
        for (int i = 1; i < 192; i += 2) if (ei_raw[i] != 0){ z = 0; break; }
        is64 = z;
        smax = 0;
    }
    if (t < 24) sdeg[t] = 1.0f;
    if (t < 576) sAl[t] = 0.0f;
    if (t >= 576 && t < 768) sw2[(t - 576)] = fcw2[t - 576];
    if (t < 64) sw2[192 + t] = fcw2[192 + t];
    __syncthreads();
    if (t < 96){
        int s, d;
        if (is64){
            const long long* e = reinterpret_cast<const long long*>(ei_raw);
            s = (int)e[t]; d = (int)e[96 + t];
        } else { s = ei_raw[t]; d = ei_raw[96 + t]; }
        s = min(max(s,0),23); d = min(max(d,0),23);
        ssrc[t] = s; sdst[t] = d;
        atomicAdd(&sdeg[d], 1.0f);
    }
    __syncthreads();
    if (t < 24) sdinv[t] = 1.0f / sqrtf(sdeg[t]);
    __syncthreads();
    if (t < 96) atomicAdd(&sAl[sdst[t]*24 + ssrc[t]], sdinv[ssrc[t]]*sdinv[sdst[t]]);
    if (t < 24) atomicAdd(&sAl[t*24 + t], sdinv[t]*sdinv[t]);
    __syncthreads();

    // ---- CSR: (a, src) pairs, 16-entry cap per node ----
    if (t < 24){
        int c = 0;
        #pragma unroll 1
        for (int j = 0; j < 24; j++){
            float a = sAl[t*24 + j];
            if (a != 0.0f && c < 16){
                g_csr[t*16 + c] = ((u64)__float_as_uint(a) << 32) | (u64)(unsigned)j;
                c++;
            }
        }
        scnt[t] = c;
        atomicMax(&smax, c);
    }
    __syncthreads();
    if (t < 24){
        for (int k = scnt[t]; k < 16; k++) g_csr[t*16 + k] = 0ull;  // a=0, src=0
    }
    if (t == 0) g_maxn = min(smax, 16);

    // ---- Wc = fcw1 @ fcw2 (padded), bc = fcb1 @ fcw2 + fcb2 ----
    {
        float a0 = 0.f, a1 = 0.f;
        const float* row = fcw1 + t * 128;
        #pragma unroll 8
        for (int k = 0; k < 128; k++){
            float w = row[k];
            a0 += w * sw2[2*k];
            a1 += w * sw2[2*k + 1];
        }
        int node = t >> 5, fi = t & 31;
        g_wc[node*66 + 2*fi]     = a0;
        g_wc[node*66 + 2*fi + 1] = a1;
        if (t < 2){
            float b = fcb2[t];
            #pragma unroll 8
            for (int k = 0; k < 128; k++) b += fcb1[k] * sw2[2*k + t];
            g_wc[1584 + t] = b;
        }
    }
}

// ---------- fused GCN kernel: warp = batch, lane = node, H in registers ----------
#define NT 256
#define TB 8

// one layer: g = A-gather via shuffles, h = relu(g.W + b)
template<int FIN, int FOUT, int W2, int B2>
__device__ __forceinline__ void gcn_layer(float* h, const u64* csr, int maxn)
{
    float g[FIN];
    #pragma unroll
    for (int f = 0; f < FIN; f++) g[f] = 0.f;
    #pragma unroll 4
    for (int k = 0; k < maxn; k++){          // maxn block-uniform -> converged shfl
        u64 e = csr[k];
        int src = (int)(unsigned)e;
        float ak = __uint_as_float((unsigned)(e >> 32));
        #pragma unroll
        for (int f = 0; f < FIN; f++)
            g[f] = fmaf(ak, __shfl_sync(0xffffffffu, h[f], src), g[f]);
    }
    constexpr int KP = FOUT/2;
    u64 acc[KP];
    #pragma unroll
    for (int k = 0; k < KP; k++) acc[k] = c_WB2[CB_B + B2 + k];
    #pragma unroll
    for (int fi = 0; fi < FIN; fi++){
        u64 d = dup2(g[fi]);
        #pragma unroll
        for (int k = 0; k < KP; k++)
            acc[k] = fma2(d, c_WB2[W2 + fi*KP + k], acc[k]);
    }
    #pragma unroll
    for (int k = 0; k < KP; k++){
        float lo, hi; upk2(acc[k], lo, hi);
        h[2*k]   = fmaxf(lo, 0.f);
        h[2*k+1] = fmaxf(hi, 0.f);
    }
}

__global__ __launch_bounds__(NT, 3)
void gcn_fused_kernel(const float* __restrict__ x, float* __restrict__ out)
{
    __shared__ float sWc[1586];
    __shared__ u64   sCsr[24*17];     // stride 17: conflict-spread
    __shared__ int   sMx;

    const int t = threadIdx.x;
    const int warp = t >> 5;
    const int lane = t & 31;

    for (int i = t; i < 1586; i += NT) sWc[i] = g_wc[i];
    for (int i = t; i < 384;  i += NT) sCsr[(i >> 4)*17 + (i & 15)] = g_csr[i];
    if (t == 0) sMx = g_maxn;

    const int node = (lane < 24) ? lane : 0;
    const u64* csr = sCsr + node * 17;
    const int gb = blockIdx.x * TB + warp;

    float h[16];
    h[0] = (lane < 24) ? x[gb*24 + lane] : 0.f;
    __syncthreads();                   // only block-wide barrier
    const int maxn = sMx;

    gcn_layer< 1,  4,   0,  0>(h, csr, maxn);
    gcn_layer< 4,  4,   2,  2>(h, csr, maxn);
    gcn_layer< 4,  8,  10,  4>(h, csr, maxn);
    gcn_layer< 8,  8,  26,  8>(h, csr, maxn);
    gcn_layer< 8, 16,  58, 12>(h, csr, maxn);
    gcn_layer<16, 16, 122, 20>(h, csr, maxn);

    // ---- layer 7 (16->32) + folded FC head, all in registers ----
    float g[16];
    #pragma unroll
    for (int f = 0; f < 16; f++) g[f] = 0.f;
    #pragma unroll 4
    for (int k = 0; k < maxn; k++){
        u64 e = csr[k];
        int src = (int)(unsigned)e;
        float ak = __uint_as_float((unsigned)(e >> 32));
        #pragma unroll
        for (int f = 0; f < 16; f++)
            g[f] = fmaf(ak, __shfl_sync(0xffffffffu, h[f], src), g[f]);
    }
    u64 z = 0ull;
    const float* wcn = sWc + node * 66;
    #pragma unroll
    for (int pass = 0; pass < 2; pass++){
        u64 acc[8];
        #pragma unroll
        for (int k = 0; k < 8; k++) acc[k] = c_WB2[CB_B + 28 + pass*8 + k];
        #pragma unroll
        for (int fi = 0; fi < 16; fi++){
            u64 d = dup2(g[fi]);
            #pragma unroll
            for (int k = 0; k < 8; k++)
                acc[k] = fma2(d, c_WB2[250 + fi*16 + pass*8 + k], acc[k]);
        }
        const float* wcp = wcn + pass * 32;
        #pragma unroll
        for (int k = 0; k < 8; k++){
            float a, b; upk2(acc[k], a, b);
            z = fma2(dup2(fmaxf(a, 0.f)), lds2(wcp + 4*k),     z);
            z = fma2(dup2(fmaxf(b, 0.f)), lds2(wcp + 4*k + 2), z);
        }
    }
    if (lane >= 24) z = 0ull;

    // ---- warp butterfly reduce over nodes + log_softmax ----
    #pragma unroll
    for (int m = 16; m >= 1; m >>= 1) z = add2(z, bfly64(z, m));
    if (lane == 0){
        z = add2(z, lds2(sWc + 1584));     // bc
        float z0, z1; upk2(z, z0, z1);
        float mx = fmaxf(z0, z1);
        float lse = mx + logf(expf(z0 - mx) + expf(z1 - mx));
        reinterpret_cast<u64*>(out)[gb] = pk2(z0 - lse, z1 - lse);
    }
}

extern "C" void kernel_launch(void* const* d_in, const int* in_sizes, int n_in,
                              void* d_out, int out_size)
{
    const float* x  = (const float*)d_in[0];
    const int*   ei = (const int*)d_in[1];
    float* out = (float*)d_out;

    const int B = in_sizes[0] / 24;
    const int grid = B / TB;           // 4096

    prologue_kernel<<<1, 768>>>(ei,
        (const float*)d_in[2],  (const float*)d_in[3],
        (const float*)d_in[4],  (const float*)d_in[5],
        (const float*)d_in[6],  (const float*)d_in[7],
        (const float*)d_in[8],  (const float*)d_in[9],
        (const float*)d_in[10], (const float*)d_in[11],
        (const float*)d_in[12], (const float*)d_in[13],
        (const float*)d_in[14], (const float*)d_in[15],
        (const float*)d_in[16], (const float*)d_in[17],
        (const float*)d_in[18], (const float*)d_in[19]);

    void* packAddr = nullptr;
    cudaGetSymbolAddress(&packAddr, g_pack);
    cudaMemcpyToSymbolAsync(c_WB2, packAddr, 1100*4, 0,
                            cudaMemcpyDeviceToDevice, 0);

    gcn_fused_kernel<<<grid, NT>>>(x, out);
}